// round 17
// baseline (speedup 1.0000x reference)
#include <cuda_runtime.h>
#include <cuda_fp16.h>
#include <math.h>
#include <stdint.h>

#define DIM       1024
#define HEADS     16
#define DIM_HEAD  64
#define HIDDEN    1024
#define BATCH     8
#define NQ        4096
#define NL        64
#define NCTX      4160
#define EPS       1e-5f

#define MKV   (BATCH * NCTX)   // 33280
#define MLAT  (BATCH * NL)     // 512
#define KDIM  1024
#define NKV   2048

#define NSPLIT 5
#define ROWS_PER_SPLIT 832
#define NTILES 13

// ---------------- scratch (device globals, allocation-free) ----------------
__device__ __align__(16) __half g_Akvh [(size_t)MKV * KDIM];
__device__ __align__(16) __half g_Alath[(size_t)MLAT * KDIM];
__device__ __align__(16) __half g_Alatl[(size_t)MLAT * KDIM];
__device__ __align__(16) __half g_Aaoh [(size_t)MLAT * HIDDEN];
__device__ __align__(16) __half g_Aaol [(size_t)MLAT * HIDDEN];
__device__ __align__(16) __half g_Bkvh [(size_t)NKV * KDIM];
__device__ __align__(16) __half g_Bqh  [(size_t)HIDDEN * KDIM];
__device__ __align__(16) __half g_Bouth[(size_t)DIM * HIDDEN];
__device__ __align__(16) __half g_Kh[(size_t)MKV * HIDDEN];
__device__ __align__(16) __half g_Vh[(size_t)MKV * HIDDEN];
__device__ float g_q [(size_t)MLAT * HIDDEN];
__device__ float g_pacc[(size_t)BATCH * HEADS * NSPLIT * NL * DIM_HEAD];
__device__ float g_pm  [(size_t)BATCH * HEADS * NSPLIT * NL];
__device__ float g_pl  [(size_t)BATCH * HEADS * NSPLIT * NL];

// ---------------- helpers ----------------
__device__ __forceinline__ void pack_hilo_h(const float* y, uint4& hv, uint4& lv) {
    union { unsigned short us[8]; uint4 v; } H, L;
    #pragma unroll
    for (int j = 0; j < 8; j++) {
        __half h = __float2half_rn(y[j]);
        float hf = __half2float(h);
        __half l = __float2half_rn(y[j] - hf);
        H.us[j] = __half_as_ushort(h);
        L.us[j] = __half_as_ushort(l);
    }
    hv = H.v; lv = L.v;
}
__device__ __forceinline__ void pack8_h(const float* y, uint4& hv) {
    union { unsigned short us[8]; uint4 v; } H;
    #pragma unroll
    for (int j = 0; j < 8; j++) H.us[j] = __half_as_ushort(__float2half_rn(y[j]));
    hv = H.v;
}
__device__ __forceinline__ void cvt_hilo4(float4 v, uint2& hv, uint2& lv) {
    union { unsigned short us[4]; uint2 u; } H, L;
    float c[4] = { v.x, v.y, v.z, v.w };
    #pragma unroll
    for (int j = 0; j < 4; j++) {
        __half h = __float2half_rn(c[j]);
        H.us[j] = __half_as_ushort(h);
        L.us[j] = __half_as_ushort(__float2half_rn(c[j] - __half2float(h)));
    }
    hv = H.u; lv = L.u;
}
__device__ __forceinline__ void reduce2_128(float& s, float& ss) {
    __shared__ float a0[4], a1[4];
    int lane = threadIdx.x & 31, w = threadIdx.x >> 5;
    #pragma unroll
    for (int o = 16; o > 0; o >>= 1) {
        s  += __shfl_down_sync(0xffffffffu, s,  o);
        ss += __shfl_down_sync(0xffffffffu, ss, o);
    }
    if (lane == 0) { a0[w] = s; a1[w] = ss; }
    __syncthreads();
    s  = a0[0] + a0[1] + a0[2] + a0[3];
    ss = a1[0] + a1[1] + a1[2] + a1[3];
}

// ---------------- LayerNorm row (128 threads) ----------------
__device__ __forceinline__ void ln_row(
    const float* __restrict__ xr, const float* __restrict__ g, const float* __restrict__ bb,
    __half* dh0, __half* dh1, __half* dl1)
{
    int t = threadIdx.x;
    float4 v0 = *(const float4*)(xr + t * 8);
    float4 v1 = *(const float4*)(xr + t * 8 + 4);
    float s  = v0.x + v0.y + v0.z + v0.w + v1.x + v1.y + v1.z + v1.w;
    float ss = v0.x*v0.x + v0.y*v0.y + v0.z*v0.z + v0.w*v0.w
             + v1.x*v1.x + v1.y*v1.y + v1.z*v1.z + v1.w*v1.w;
    reduce2_128(s, ss);
    float mean = s * (1.0f / DIM);
    float inv  = rsqrtf(ss * (1.0f / DIM) - mean * mean + EPS);
    float4 g0 = *(const float4*)(g + t * 8),  g1 = *(const float4*)(g + t * 8 + 4);
    float4 b0 = *(const float4*)(bb + t * 8), b1 = *(const float4*)(bb + t * 8 + 4);
    float y[8];
    y[0] = (v0.x - mean) * inv * g0.x + b0.x;
    y[1] = (v0.y - mean) * inv * g0.y + b0.y;
    y[2] = (v0.z - mean) * inv * g0.z + b0.z;
    y[3] = (v0.w - mean) * inv * g0.w + b0.w;
    y[4] = (v1.x - mean) * inv * g1.x + b1.x;
    y[5] = (v1.y - mean) * inv * g1.y + b1.y;
    y[6] = (v1.z - mean) * inv * g1.z + b1.z;
    y[7] = (v1.w - mean) * inv * g1.w + b1.w;
    uint4 hv, lv; pack_hilo_h(y, hv, lv);
    *(uint4*)(dh0 + t * 8) = hv;
    if (dh1) {
        *(uint4*)(dh1 + t * 8) = hv;
        *(uint4*)(dl1 + t * 8) = lv;
    }
}

// ---------------- weight convert body (128 threads/block) ----------------
__device__ __forceinline__ void conv_w_body(
    const float* __restrict__ W, __half* __restrict__ Bh, int K, int N, int blk)
{
    int idx = blk * 128 + threadIdx.x;
    int n  = idx / (K >> 3);
    int k0 = (idx - n * (K >> 3)) << 3;
    float y[8];
    #pragma unroll
    for (int j = 0; j < 8; j++) y[j] = W[(size_t)(k0 + j) * N + n];
    uint4 hv; pack8_h(y, hv);
    *(uint4*)(Bh + (size_t)n * K + k0) = hv;
}

// ---------------- fused prep ----------------
#define PREP_LNX   (BATCH * NQ)
#define PREP_LNL   (PREP_LNX + BATCH * NL)
#define PREP_WKV   (PREP_LNL + (NKV * (KDIM / 8)) / 128)
#define PREP_WQ    (PREP_WKV + (HIDDEN * (KDIM / 8)) / 128)
#define PREP_WOUT  (PREP_WQ  + (DIM * (HIDDEN / 8)) / 128)

__global__ void __launch_bounds__(128) prep_kernel(
    const float* __restrict__ x, const float* __restrict__ latents,
    const float* __restrict__ gm, const float* __restrict__ bm,
    const float* __restrict__ gl, const float* __restrict__ bl,
    const float* __restrict__ Wkv, const float* __restrict__ Wq,
    const float* __restrict__ Wout)
{
    int blk = blockIdx.x;
    if (blk < PREP_LNX) {
        int row = blk;
        int b = row >> 12, i = row & (NQ - 1);
        size_t m = (size_t)(b * NCTX + i) * KDIM;
        ln_row(x + (size_t)row * DIM, gm, bm, g_Akvh + m, nullptr, nullptr);
    } else if (blk < PREP_LNL) {
        int row = blk - PREP_LNX;
        int b = row >> 6, i = row & (NL - 1);
        size_t mkv = (size_t)(b * NCTX + NQ + i) * KDIM;
        size_t mlt = (size_t)row * KDIM;
        ln_row(latents + (size_t)row * DIM, gl, bl,
               g_Akvh + mkv, g_Alath + mlt, g_Alatl + mlt);
    } else if (blk < PREP_WKV) {
        conv_w_body(Wkv, g_Bkvh, KDIM, NKV, blk - PREP_LNL);
    } else if (blk < PREP_WQ) {
        conv_w_body(Wq, g_Bqh, KDIM, HIDDEN, blk - PREP_WKV);
    } else {
        conv_w_body(Wout, g_Bouth, HIDDEN, DIM, blk - PREP_WQ);
    }
}

// ---------------- common GEMM primitives ----------------
#define SAB 80
__device__ __forceinline__ void cp16(uint32_t dst, const void* src) {
    asm volatile("cp.async.cg.shared.global [%0], [%1], 16;" :: "r"(dst), "l"(src) : "memory");
}
__device__ __forceinline__ void ldsm4(uint32_t* r, uint32_t addr) {
    asm volatile("ldmatrix.sync.aligned.m8n8.x4.shared.b16 {%0,%1,%2,%3}, [%4];"
                 : "=r"(r[0]), "=r"(r[1]), "=r"(r[2]), "=r"(r[3]) : "r"(addr));
}
__device__ __forceinline__ void ldsm4t(uint32_t* r, uint32_t addr) {
    asm volatile("ldmatrix.sync.aligned.m8n8.x4.trans.shared.b16 {%0,%1,%2,%3}, [%4];"
                 : "=r"(r[0]), "=r"(r[1]), "=r"(r[2]), "=r"(r[3]) : "r"(addr));
}
__device__ __forceinline__ void mma16816h(float* c, const uint32_t* a, uint32_t b0, uint32_t b1) {
    asm volatile(
        "mma.sync.aligned.m16n8k16.row.col.f32.f16.f16.f32 "
        "{%0,%1,%2,%3}, {%4,%5,%6,%7}, {%8,%9}, {%0,%1,%2,%3};"
        : "+f"(c[0]), "+f"(c[1]), "+f"(c[2]), "+f"(c[3])
        : "r"(a[0]), "r"(a[1]), "r"(a[2]), "r"(a[3]), "r"(b0), "r"(b1));
}

// ---------------- BIG GEMM (kv): BM=128 BN=256 BK=32, 512 thr, 4-stage, 1-pass fp16 ----------------
#define A_PLANE (128 * SAB)
#define B_PLANE (256 * SAB)
#define STAGE_BG (A_PLANE + B_PLANE)
#define NSTAGE_BG 4
#define GEMM_SMEM_BG (NSTAGE_BG * STAGE_BG)

__global__ void __launch_bounds__(512, 1) gemm_f16x1_big(
    const __half* __restrict__ Ah, const __half* __restrict__ Bh, int M, int N, int K)
{
    extern __shared__ unsigned char smraw[];
    uint32_t sbase = (uint32_t)__cvta_generic_to_shared(smraw);
    int tid = threadIdx.x;
    int wid = tid >> 5, lane = tid & 31;
    int wm = wid & 1, wn = wid >> 1;
    int m0 = blockIdx.y * 128, n0 = blockIdx.x * 256;
    const int NC = K >> 5;
    const bool kSide = (n0 < HIDDEN);

    int lrow = tid >> 2;
    int lcol = tid & 3;

    float acc[4][4][4];
    #pragma unroll
    for (int i = 0; i < 4; i++)
        #pragma unroll
        for (int j = 0; j < 4; j++)
            #pragma unroll
            for (int e = 0; e < 4; e++) acc[i][j][e] = 0.f;

    #define LOAD_STAGE_BG(kc, s) do {                                                 \
        uint32_t st_ = sbase + (uint32_t)(s) * STAGE_BG;                               \
        int k0_ = (kc) * 32;                                                           \
        cp16(st_ + lrow * SAB + lcol * 16,                                             \
             Ah + (size_t)(m0 + lrow) * K + k0_ + lcol * 8);                           \
        uint32_t bh_ = st_ + A_PLANE;                                                  \
        cp16(bh_ + lrow * SAB + lcol * 16,                                             \
             Bh + (size_t)(n0 + lrow) * K + k0_ + lcol * 8);                           \
        cp16(bh_ + (lrow + 128) * SAB + lcol * 16,                                     \
             Bh + (size_t)(n0 + lrow + 128) * K + k0_ + lcol * 8);                     \
    } while (0)

    LOAD_STAGE_BG(0, 0);
    asm volatile("cp.async.commit_group;" ::: "memory");
    LOAD_STAGE_BG(1, 1);
    asm volatile("cp.async.commit_group;" ::: "memory");
    LOAD_STAGE_BG(2, 2);
    asm volatile("cp.async.commit_group;" ::: "memory");

    int frow = lane & 15;
    int fcolb = (lane >> 4) * 16;
    uint32_t arow = (uint32_t)(wm * 64 + frow) * SAB;
    uint32_t brow = (uint32_t)(wn * 32 + frow) * SAB;

    for (int c = 0; c < NC; c++) {
        asm volatile("cp.async.wait_group 2;" ::: "memory");
        __syncthreads();

        if (c + 3 < NC) { LOAD_STAGE_BG(c + 3, (c + 3) % NSTAGE_BG); }
        asm volatile("cp.async.commit_group;" ::: "memory");

        uint32_t sst = sbase + (uint32_t)(c % NSTAGE_BG) * STAGE_BG;
        uint32_t aHp = sst, bHp = sst + A_PLANE;

        #pragma unroll
        for (int ks = 0; ks < 2; ks++) {
            uint32_t colb = (uint32_t)(ks * 32) + fcolb;
            uint32_t fa[4][4], fb[2][4];
            #pragma unroll
            for (int mt = 0; mt < 4; mt++) ldsm4(fa[mt], aHp + arow + mt * (16 * SAB) + colb);
            #pragma unroll
            for (int g = 0; g < 2; g++)    ldsm4(fb[g], bHp + brow + g * (16 * SAB) + colb);
            #pragma unroll
            for (int mt = 0; mt < 4; mt++)
                #pragma unroll
                for (int nt = 0; nt < 4; nt++) {
                    int g = nt >> 1, o = nt & 1;
                    mma16816h(acc[mt][nt], fa[mt], fb[g][o], fb[g][o + 2]);
                }
        }
    }
    #undef LOAD_STAGE_BG

    int rbase = m0 + wm * 64 + (lane >> 2);
    int cbase0 = n0 + wn * 32 + (lane & 3) * 2;
    __half* dstp = kSide ? g_Kh : g_Vh;
    int coff = kSide ? 0 : HIDDEN;
    #pragma unroll
    for (int mt = 0; mt < 4; mt++) {
        #pragma unroll
        for (int nt = 0; nt < 4; nt++) {
            int r = rbase + mt * 16, cc = cbase0 + nt * 8 - coff;
            __half2 h0 = __floats2half2_rn(acc[mt][nt][0], acc[mt][nt][1]);
            __half2 h1 = __floats2half2_rn(acc[mt][nt][2], acc[mt][nt][3]);
            *(__half2*)(dstp + (size_t)r * HIDDEN + cc)       = h0;
            *(__half2*)(dstp + (size_t)(r + 8) * HIDDEN + cc) = h1;
        }
    }
}

// ---------------- SMALL GEMM (q/out): BM=64 BN=128 BK=32, 128 thr, 3-stage, 2-pass ----------------
#define SA64 (64 * SAB)
#define STAGE_S2 (2 * SA64 + 128 * SAB)
#define NSTAGE_S2 3
#define GEMM_SMEM_S2 (NSTAGE_S2 * STAGE_S2)

__global__ void __launch_bounds__(128, 3) gemm_f16x2_s64(
    const __half* __restrict__ Ah, const __half* __restrict__ Al,
    const __half* __restrict__ Bh,
    float* __restrict__ C, int M, int N, int K)
{
    extern __shared__ unsigned char smraw[];
    uint32_t sbase = (uint32_t)__cvta_generic_to_shared(smraw);
    int tid = threadIdx.x;
    int wid = tid >> 5, lane = tid & 31;
    int wm = wid & 1, wn = wid >> 1;
    int m0 = blockIdx.y * 64, n0 = blockIdx.x * 128;
    const int NC = K >> 5;

    int lrow4 = tid >> 2;
    int lcol4 = tid & 3;

    float acc[2][8][4];
    #pragma unroll
    for (int i = 0; i < 2; i++)
        #pragma unroll
        for (int j = 0; j < 8; j++)
            #pragma unroll
            for (int e = 0; e < 4; e++) acc[i][j][e] = 0.f;

    #define LOAD_STAGE_S2(kc, s) do {                                                 \
        uint32_t st_ = sbase + (uint32_t)(s) * STAGE_S2;                               \
        int k0_ = (kc) * 32;                                                           \
        _Pragma("unroll")                                                              \
        for (int rr = 0; rr < 2; rr++) {                                               \
            int row_ = lrow4 + rr * 32;                                                \
            cp16(st_ + row_ * SAB + lcol4 * 16,                                        \
                 Ah + (size_t)(m0 + row_) * K + k0_ + lcol4 * 8);                      \
            cp16(st_ + SA64 + row_ * SAB + lcol4 * 16,                                 \
                 Al + (size_t)(m0 + row_) * K + k0_ + lcol4 * 8);                      \
        }                                                                              \
        _Pragma("unroll")                                                              \
        for (int rr = 0; rr < 4; rr++) {                                               \
            int row_ = lrow4 + rr * 32;                                                \
            cp16(st_ + 2 * SA64 + row_ * SAB + lcol4 * 16,                             \
                 Bh + (size_t)(n0 + row_) * K + k0_ + lcol4 * 8);                      \
        }                                                                              \
    } while (0)

    LOAD_STAGE_S2(0, 0);
    asm volatile("cp.async.commit_group;" ::: "memory");
    LOAD_STAGE_S2(1, 1);
    asm volatile("cp.async.commit_group;" ::: "memory");

    int frow = lane & 15;
    int fcolb = (lane >> 4) * 16;
    uint32_t arow = (uint32_t)(wm * 32 + frow) * SAB;
    uint32_t brow = (uint32_t)(wn * 64 + frow) * SAB;

    for (int c = 0; c < NC; c++) {
        asm volatile("cp.async.wait_group 1;" ::: "memory");
        __syncthreads();

        if (c + 2 < NC) { LOAD_STAGE_S2(c + 2, (c + 2) % NSTAGE_S2); }
        asm volatile("cp.async.commit_group;" ::: "memory");

        uint32_t sst = sbase + (uint32_t)(c % NSTAGE_S2) * STAGE_S2;
        uint32_t aHp = sst, aLp = sst + SA64;
        uint32_t bHp = sst + 2 * SA64;

        #pragma unroll
        for (int ks = 0; ks < 2; ks++) {
            uint32_t colb = (uint32_t)(ks * 32) + fcolb;
            uint32_t fa[2][4], fl[2][4], fb[4][4];
            #pragma unroll
            for (int mt = 0; mt < 2; mt++) ldsm4(fa[mt], aHp + arow + mt * (16 * SAB) + colb);
            #pragma unroll
            for (int g = 0; g < 4; g++)    ldsm4(fb[g], bHp + brow + g * (16 * SAB) + colb);
            #pragma unroll
            for (int mt = 0; mt < 2; mt++) ldsm4(fl[mt], aLp + arow + mt * (16 * SAB) + colb);
            #pragma unroll
            for (int mt = 0; mt < 2; mt++)
                #pragma unroll
                for (int nt = 0; nt < 8; nt++) {
                    int g = nt >> 1, o = nt & 1;
                    mma16816h(acc[mt][nt], fa[mt], fb[g][o], fb[g][o + 2]);
                }
            #pragma unroll
            for (int mt = 0; mt < 2; mt++)
                #pragma unroll
                for (int nt = 0; nt < 8; nt++) {
                    int g = nt >> 1, o = nt & 1;
                    mma16816h(acc[mt][nt], fl[mt], fb[g][o], fb[g][o + 2]);
                }
        }
    }
    #undef LOAD_STAGE_S2

    int rbase = m0 + wm * 32 + (lane >> 2);
    int cbase = n0 + wn * 64 + (lane & 3) * 2;
    #pragma unroll
    for (int mt = 0; mt < 2; mt++) {
        #pragma unroll
        for (int nt = 0; nt < 8; nt++) {
            int r = rbase + mt * 16, cc = cbase + nt * 8;
            *(float2*)(C + (size_t)r * N + cc)       = make_float2(acc[mt][nt][0], acc[mt][nt][1]);
            *(float2*)(C + (size_t)(r + 8) * N + cc) = make_float2(acc[mt][nt][2], acc[mt][nt][3]);
        }
    }
}

// ---------------- attention stage 1: fp16 MMA flash, parallel softmax ----------------
#define HST  72
#define PST  69
#define T16B (64 * HST * 2)
#define STGB (2 * T16B)

__global__ void __launch_bounds__(256) attn_split_kernel()
{
    extern __shared__ unsigned char smc[];
    __half* qh  = (__half*)smc;
    __half* p16 = (__half*)(smc + 2 * T16B + 2 * STGB);
    float*  psT = (float*)(smc + 3 * T16B + 2 * STGB);
    float*  m_s = psT + 64 * PST;
    float*  l_s = m_s + 64;
    float*  a_s = l_s + 64;

    uint32_t SQH  = (uint32_t)__cvta_generic_to_shared(qh);
    uint32_t SQL  = SQH + T16B;
    uint32_t SBUF = SQL + T16B;
    uint32_t SP   = SBUF + 2 * STGB;

    int bh = blockIdx.x, sp = blockIdx.y;
    int b = bh >> 4, h = bh & 15;
    int tid = threadIdx.x;
    int wid = tid >> 5, lane = tid & 31;
    int wq = wid & 3, wh = wid >> 2;
    int frow = lane & 15;
    int fcolb = (lane >> 4) * 16;

    const float* qg = g_q + ((size_t)(b * NL)) * HIDDEN + h * DIM_HEAD;
    __half* ql = qh + 64 * HST;
    for (int f = tid; f < 64 * 16; f += 256) {
        int r = f >> 4, c4 = (f & 15) << 2;
        float4 v = *(const float4*)(qg + (size_t)r * HIDDEN + c4);
        uint2 hv, lv; cvt_hilo4(v, hv, lv);
        *(uint2*)(qh + r * HST + c4) = hv;
        *(uint2*)(ql + r * HST + c4) = lv;
    }
    if (tid < 64) { m_s[tid] = -INFINITY; l_s[tid] = 0.f; }

    float acc[4][4];
    #pragma unroll
    for (int nt = 0; nt < 4; nt++)
        #pragma unroll
        for (int e = 0; e < 4; e++) acc[nt][e] = 0.f;

    size_t rowbase = (size_t)(b * NCTX) * HIDDEN + h * DIM_HEAD;
    const __half* gpK = g_Kh + rowbase;
    const __half* gpV = g_Vh + rowbase;

    int s_begin = sp * ROWS_PER_SPLIT;

    // softmax lane mapping: 4 lanes per query
    int sq  = tid >> 2;          // query 0..63
    int sub = tid & 3;           // 16-score strip

    #define LOAD_TILE(t_, stg_) do {                                                   \
        int srow0_ = s_begin + (t_) * 64;                                              \
        uint32_t dst0_ = SBUF + (uint32_t)(stg_) * STGB;                                \
        _Pragma("unroll")                                                               \
        for (int j_ = 0; j_ < 4; j_++) {                                                \
            int idx_ = tid + j_ * 256;                                                  \
            int pl_ = idx_ >> 9;                                                        \
            int r_ = (idx_ & 511) >> 3;                                                 \
            int c_ = idx_ & 7;                                                          \
            const __half* sp_ = pl_ ? gpV : gpK;                                        \
            cp16(dst0_ + pl_ * T16B + r_ * (HST * 2) + c_ * 16,                         \
                 sp_ + (size_t)(srow0_ + r_) * HIDDEN + c_ * 8);                        \
        }                                                                               \
    } while (0)

    LOAD_TILE(0, 0);
    asm volatile("cp.async.commit_group;" ::: "memory");

    for (int t = 0; t < NTILES; t++) {
        __syncthreads();
        if (t + 1 < NTILES) { LOAD_TILE(t + 1, (t + 1) & 1); }
        asm volatile("cp.async.commit_group;" ::: "memory");
        asm volatile("cp.async.wait_group 1;" ::: "memory");
        __syncthreads();

        uint32_t SKH = SBUF + (uint32_t)(t & 1) * STGB;
        uint32_t SVH = SKH + T16B;

        // ---- QK^T (2 passes) ----
        {
            float sc[4][4];
            #pragma unroll
            for (int nt = 0; nt < 4; nt++)
                #pragma unroll
                for (int e = 0; e < 4; e++) sc[nt][e] = 0.f;
            uint32_t qrow = (uint32_t)(wq * 16 + frow) * (HST * 2);
            uint32_t srow = (uint32_t)(wh * 32 + frow) * (HST * 2);
            #pragma unroll
            for (int kd = 0; kd < 4; kd++) {
                uint32_t colb = (uint32_t)(kd * 32) + fcolb;
                uint32_t fqh[4], fql[4], fkh[2][4];
                ldsm4(fqh, SQH + qrow + colb);
                ldsm4(fql, SQL + qrow + colb);
                #pragma unroll
                for (int g = 0; g < 2; g++)
                    ldsm4(fkh[g], SKH + srow + g * (16 * HST * 2) + colb);
                #pragma unroll
                for (int nt = 0; nt < 4; nt++) {
                    int g = nt >> 1, o = nt & 1;
                    mma16816h(sc[nt], fqh, fkh[g][o], fkh[g][o + 2]);
                    mma16816h(sc[nt], fql, fkh[g][o], fkh[g][o + 2]);
                }
            }
            int r0 = wq * 16 + (lane >> 2);
            int cb = wh * 32 + (lane & 3) * 2;
            #pragma unroll
            for (int nt = 0; nt < 4; nt++) {
                int cc = cb + nt * 8;
                psT[r0 * PST + cc]           = sc[nt][0];
                psT[r0 * PST + cc + 1]       = sc[nt][1];
                psT[(r0 + 8) * PST + cc]     = sc[nt][2];
                psT[(r0 + 8) * PST + cc + 1] = sc[nt][3];
            }
        }
        __syncthreads();

        // ---- online softmax: 4 lanes per query, shuffle reduce ----
        {
            float mo = m_s[sq];
            float mt = mo;
            int s0 = sub * 16;
            #pragma unroll
            for (int s = 0; s < 16; s++) mt = fmaxf(mt, psT[sq * PST + s0 + s]);
            mt = fmaxf(mt, __shfl_xor_sync(0xffffffffu, mt, 1));
            mt = fmaxf(mt, __shfl_xor_sync(0xffffffffu, mt, 2));
            float lsum = 0.f;
            #pragma unroll
            for (int s = 0; s < 16; s += 2) {
                float e0 = __expf(psT[sq * PST + s0 + s] - mt);
                float e1 = __expf(psT[sq * PST + s0 + s + 1] - mt);
                lsum += e0 + e1;
                *(__half2*)(p16 + sq * HST + s0 + s) = __floats2half2_rn(e0, e1);
            }
            lsum += __shfl_xor_sync(0xffffffffu, lsum, 1);
            lsum += __shfl_xor_sync(0xffffffffu, lsum, 2);
            if (sub == 0) {
                float al = __expf(mo - mt);
                m_s[sq] = mt;
                l_s[sq] = l_s[sq] * al + lsum;
                a_s[sq] = al;
            }
        }
        __syncthreads();

        // ---- PV (1 pass) ----
        {
            int r0 = wq * 16 + (lane >> 2);
            float a0 = a_s[r0], a1 = a_s[r0 + 8];
            #pragma unroll
            for (int nt = 0; nt < 4; nt++) {
                acc[nt][0] *= a0; acc[nt][1] *= a0;
                acc[nt][2] *= a1; acc[nt][3] *= a1;
            }
            uint32_t prow = (uint32_t)(wq * 16 + frow) * (HST * 2);
            #pragma unroll
            for (int ks = 0; ks < 4; ks++) {
                uint32_t fp[4], fvh[2][4];
                ldsm4(fp, SP + prow + ks * 32 + fcolb);
                uint32_t vrow = (uint32_t)(ks * 16 + frow) * (HST * 2);
                #pragma unroll
                for (int g = 0; g < 2; g++) {
                    uint32_t coldb = (uint32_t)(wh * 32 + g * 16) * 2 + fcolb;
                    ldsm4t(fvh[g], SVH + vrow + coldb);
                }
                #pragma unroll
                for (int nt = 0; nt < 4; nt++) {
                    int g = nt >> 1, o = nt & 1;
                    mma16816h(acc[nt], fp, fvh[g][2 * o], fvh[g][2 * o + 1]);
                }
            }
        }
    }
    #undef LOAD_TILE

    {
        int r0 = wq * 16 + (lane >> 2);
        int cb = wh * 32 + (lane & 3) * 2;
        size_t base = ((size_t)(bh * NSPLIT + sp) * NL) * DIM_HEAD;
        #pragma unroll
        for (int nt = 0; nt < 4; nt++) {
            int cc = cb + nt * 8;
            *(float2*)(g_pacc + base + (size_t)r0 * DIM_HEAD + cc) =
                make_float2(acc[nt][0], acc[nt][1]);
            *(float2*)(g_pacc + base + (size_t)(r0 + 8) * DIM_HEAD + cc) =
                make_float2(acc[nt][2], acc[nt][3]);
        }
    }
    if (tid < 64) {
        size_t mb = (size_t)(bh * NSPLIT + sp) * NL + tid;
        g_pm[mb] = m_s[tid];
        g_pl[mb] = l_s[tid];
    }
}

// ---------------- attention stage 2: combine splits (4 rows per block) ----------------
__global__ void __launch_bounds__(256) attn_reduce_kernel()
{
    __shared__ float sw[4][NSPLIT];
    __shared__ float sinv[4];

    int rgrp = threadIdx.x >> 6;          // 0..3 (row within block)
    int row = blockIdx.x * 4 + rgrp;
    int bh = row >> 6, q = row & 63;
    int b = bh >> 4, h = bh & 15;
    int d = threadIdx.x & 63;

    if (d == 0) {
        float m[NSPLIT], l[NSPLIT];
        float mstar = -INFINITY;
        #pragma unroll
        for (int s = 0; s < NSPLIT; s++) {
            size_t mb = (size_t)(bh * NSPLIT + s) * NL + q;
            m[s] = g_pm[mb]; l[s] = g_pl[mb];
            mstar = fmaxf(mstar, m[s]);
        }
        float lstar = 0.f;
        #pragma unroll
        for (int s = 0; s < NSPLIT; s++) {
            float w = __expf(m[s] - mstar);
            sw[rgrp][s] = w;
            lstar += w * l[s];
        }
        sinv[rgrp] = 1.0f / (lstar * 8.0f);
    }
    __syncthreads();

    float comb = 0.f;
    #pragma unroll
    for (int s = 0; s < NSPLIT; s++) {
        size_t pb = ((size_t)(bh * NSPLIT + s) * NL + q) * DIM_HEAD + d;
        comb = fmaf(sw[rgrp][s], g_pacc[pb], comb);
    }
    float y = comb * sinv[rgrp];

    size_t o = (size_t)(b * NL + q) * HIDDEN + h * DIM_HEAD + d;
    __half hi = __float2half_rn(y);
    __half lo = __float2half_rn(y - __half2float(hi));
    g_Aaoh[o] = hi;
    g_Aaol[o] = lo;
}

// ---------------- launch ----------------
extern "C" void kernel_launch(void* const* d_in, const int* in_sizes, int n_in,
                              void* d_out, int out_size)
{
    const float* x       = (const float*)d_in[0];
    const float* latents = (const float*)d_in[1];
    const float* gm      = (const float*)d_in[2];
    const float* bm      = (const float*)d_in[3];
    const float* gl      = (const float*)d_in[4];
    const float* bl      = (const float*)d_in[5];
    const float* Wq      = (const float*)d_in[6];
    const float* Wkv     = (const float*)d_in[7];
    const float* Wout    = (const float*)d_in[8];
    float* out = (float*)d_out;

    void *pAkvh, *pAlath, *pAlatl, *pAaoh, *pAaol;
    void *pBkvh, *pBqh, *pBouth, *pq;
    cudaGetSymbolAddress(&pAkvh, g_Akvh);
    cudaGetSymbolAddress(&pAlath, g_Alath); cudaGetSymbolAddress(&pAlatl, g_Alatl);
    cudaGetSymbolAddress(&pAaoh, g_Aaoh);   cudaGetSymbolAddress(&pAaol, g_Aaol);
    cudaGetSymbolAddress(&pBkvh, g_Bkvh);
    cudaGetSymbolAddress(&pBqh, g_Bqh);
    cudaGetSymbolAddress(&pBouth, g_Bouth);
    cudaGetSymbolAddress(&pq, g_q);

    cudaFuncSetAttribute(gemm_f16x1_big, cudaFuncAttributeMaxDynamicSharedMemorySize, GEMM_SMEM_BG);
    cudaFuncSetAttribute(gemm_f16x2_s64, cudaFuncAttributeMaxDynamicSharedMemorySize, GEMM_SMEM_S2);
    int attn_smem = 3 * T16B + 2 * STGB + 64 * PST * 4 + 3 * 64 * 4;
    cudaFuncSetAttribute(attn_split_kernel, cudaFuncAttributeMaxDynamicSharedMemorySize, attn_smem);

    // 1: fused prep
    prep_kernel<<<PREP_WOUT, 128>>>(x, latents, gm, bm, gl, bl, Wkv, Wq, Wout);
    // 2: kv GEMM -> fp16 K/V planes
    gemm_f16x1_big<<<dim3(NKV / 256, MKV / 128), 512, GEMM_SMEM_BG>>>(
        (const __half*)pAkvh, (const __half*)pBkvh, MKV, NKV, KDIM);
    // 3: q GEMM
    gemm_f16x2_s64<<<dim3(HIDDEN / 128, MLAT / 64), 128, GEMM_SMEM_S2>>>(
        (const __half*)pAlath, (const __half*)pAlatl, (const __half*)pBqh,
        (float*)pq, MLAT, HIDDEN, KDIM);
    // 4,5: attention
    attn_split_kernel<<<dim3(BATCH * HEADS, NSPLIT), 256, attn_smem>>>();
    attn_reduce_kernel<<<(BATCH * HEADS * NL) / 4, 256>>>();
    // 6: out GEMM
    gemm_f16x2_s64<<<dim3(DIM / 128, MLAT / 64), 128, GEMM_SMEM_S2>>>(
        (const __half*)pAaoh, (const __half*)pAaol, (const __half*)pBouth,
        out, MLAT, DIM, HIDDEN);
}